// round 17
// baseline (speedup 1.0000x reference)
#include <cuda_runtime.h>
#include <math.h>

#define NLEV   16
#define NDENSE 12
#define NCONS  4
#define TSIZE  524288
#define HPRIME 2654435761u
#define HMASK  524287u
#define BLK    256          // fill kernel block
#define BLKT   192          // main kernel: 6 warps
#define DPTS   64           // points per dense block (192 thr / 3)
#define HPTS   96           // points per hash block  (192 thr / 2)

// Dense-level resolutions (float32 np.power chain margins all >> ulp error).
__device__ __constant__ int   RESD[NDENSE] = {16,22,30,42,58,80,111,153,212,294,406,561};
__device__ __constant__ float GSD[NDENSE] = {
    (float)(2048.0/16.0),  (float)(2048.0/22.0),  (float)(2048.0/30.0),
    (float)(2048.0/42.0),  (float)(2048.0/58.0),  (float)(2048.0/80.0),
    (float)(2048.0/111.0), (float)(2048.0/153.0), (float)(2048.0/212.0),
    (float)(2048.0/294.0), (float)(2048.0/406.0), (float)(2048.0/561.0)
};

// Quad table: g_quad[(QOFF[l]+c)*8 ..] = table_l[c], table_l[c+1],
// table_l[c+res], table_l[c+res+1] (8 floats = 32B per cell).
// One 32B v8 load fetches ALL FOUR corners of a dense cell.
#define QTOTAL 661844
__device__ __align__(32) float g_quad[QTOTAL * 8];
__constant__ int QOFF[13] = {0,274,782,1714,3522,6946,13428,25862,49426,
                             94584,181316,346560,661844};

// Build the quad table (runs inside the captured graph; coalesced, few us).
__global__ void fill_quad_kernel(const float* __restrict__ tables)
{
    int idx = blockIdx.x * BLK + threadIdx.x;
    if (idx >= QTOTAL) return;
    int l = 0;
#pragma unroll
    for (int i = 1; i < NDENSE; i++) if (idx >= QOFF[i]) l = i;
    int c   = idx - QOFF[l];
    int res = RESD[l];
    const float2* tb2 = (const float2*)tables + (size_t)l * TSIZE;
    float2 e0 = __ldg(tb2 + c);
    float2 e1 = __ldg(tb2 + c + 1);
    float2 e2 = __ldg(tb2 + c + res);
    float2 e3 = __ldg(tb2 + c + res + 1);
    float* q = g_quad + (size_t)idx * 8;
    *(float4*)q       = make_float4(e0.x, e0.y, e1.x, e1.y);
    *(float4*)(q + 4) = make_float4(e2.x, e2.y, e3.x, e3.y);
}

// XLA:GPU emits approximate full-range division (div.full.f32) for f32 divide.
// Required for bit-exact bl = floor(x/gs) at cell boundaries.
__device__ __forceinline__ float div_full(float a, float b)
{
    float r;
    asm("div.full.f32 %0, %1, %2;" : "=f"(r) : "f"(a), "f"(b));
    return r;
}

// Exact replica of jnp.searchsorted(tk_row, 2h) -> where(k==n,0,k) -> tv[k].
__device__ __forceinline__ int cons_lookup(const int* __restrict__ tk,
                                           const int* __restrict__ tv,
                                           long long rowoff, int n, unsigned h)
{
    int q  = 2 * (int)h;
    int lo = 0, hi = n;
    while (lo < hi) {
        int mid = (lo + hi) >> 1;
        if (__ldg(tk + rowoff + mid) < q) lo = mid + 1; else hi = mid;
    }
    if (lo == n) lo = 0;
    return __ldg(tv + rowoff + lo);
}

// HOMOGENEOUS BLOCKS, ROLES INTERLEAVED IN DISPATCH ORDER.
// CTAs dispatch in ascending blockIdx; Nd:Nh = 3:2 exactly, so every group of
// 5 consecutive blocks = 3 dense + 2 hash. Each SM therefore holds a mix of
// load-heavy hash blocks and compute-heavier dense blocks at ALL times (the
// R16 layout ran a dense phase then a pure-hash phase), and the tail is mixed.
//   dense block: 192 thr = 64 pts (3 thr/pt, g -> levels {4g..4g+3});
//                4 x 32B v8 quad loads per thread.
//   hash block:  192 thr = 96 pts (2 thr/pt, half -> levels {12+2h,13+2h});
//                8 random loads per thread.
// CONS params inline from lengths (exact recovery); div.full for bl
// (bit-exact); __fdividef for w (feats-only, ~2ulp).
__global__ __launch_bounds__(BLKT, 8)
void hashgrid_kernel(const float* __restrict__ x,
                     const float* __restrict__ tables,
                     const int*   __restrict__ tk,
                     const int*   __restrict__ tv,
                     const int*   __restrict__ lengths,
                     int L, int maxP,
                     float* __restrict__ out,
                     int npts)
{
    const int tid = threadIdx.x;
    const size_t idxbase = (size_t)npts * 32;

    const int grp = blockIdx.x / 5;
    const int rem = blockIdx.x - 5 * grp;

    if (rem < 3) {
        // ---------------- dense block (dIdx = grp*3 + rem) ----------------
        const int dIdx = grp * 3 + rem;
        const int pt = tid / 3;               // 0..63
        const int g  = tid - 3 * pt;          // 0..2
        const int p  = dIdx * DPTS + pt;
        const bool valid = (p < npts);
        const int  pl = valid ? p : (npts - 1);
        const int lvl0 = 4 * g;

        const float2 xv = __ldg((const float2*)x + pl);
        const float x0 = xv.x, x1 = xv.y;

        float w0s[4], w1s[4], f[8];
        int cells[4];
#pragma unroll
        for (int j = 0; j < 4; j++) {
            const int lvl = lvl0 + j;
            const int   res = RESD[lvl];
            const float gs  = GSD[lvl];

            float q0  = div_full(x0, gs);
            float q1  = div_full(x1, gs);
            float b0f = floorf(q0), b1f = floorf(q1);
            int   b0  = (int)b0f,   b1  = (int)b1f;
            float mn0 = b0f * gs,   mn1 = b1f * gs;
            w0s[j] = __fdividef(x0 - mn0, (mn0 + gs) - mn0);
            w1s[j] = __fdividef(x1 - mn1, (mn1 + gs) - mn1);

            int i00 = b0 * res + b1;
            cells[j] = i00;

            if (valid) {
                float4 v = make_float4((float)i00, (float)(i00 + 1),
                                       (float)(i00 + res), (float)(i00 + res + 1));
                __stcs((float4*)(out + idxbase + ((size_t)lvl * npts + p) * 4), v);
            }
        }

#pragma unroll
        for (int j = 0; j < 4; j++) {
            const int lvl = lvl0 + j;
            const float* qp = g_quad + (size_t)(QOFF[lvl] + cells[j]) * 8;
            float r0, r1, r2, r3, r4, r5, r6, r7;
            asm("ld.global.v8.f32 {%0,%1,%2,%3,%4,%5,%6,%7}, [%8];"
                : "=f"(r0), "=f"(r1), "=f"(r2), "=f"(r3),
                  "=f"(r4), "=f"(r5), "=f"(r6), "=f"(r7)
                : "l"(qp));

            float w0 = w0s[j], w1 = w1s[j];
            float om0 = 1.0f - w0, om1 = 1.0f - w1;
            float c0x = r0 * om1 + r2 * w1;
            float c0y = r1 * om1 + r3 * w1;
            float c1x = r4 * om1 + r6 * w1;
            float c1y = r5 * om1 + r7 * w1;
            f[2 * j]     = c0x * om0 + c1x * w0;
            f[2 * j + 1] = c0y * om0 + c1y * w0;
        }

        if (valid) {
            float* dst = out + (size_t)p * 32 + 8 * g;   // 32B-aligned slice
            asm volatile(
                "st.global.cs.v8.f32 [%0], {%1,%2,%3,%4,%5,%6,%7,%8};"
                :: "l"(dst),
                   "f"(f[0]), "f"(f[1]), "f"(f[2]), "f"(f[3]),
                   "f"(f[4]), "f"(f[5]), "f"(f[6]), "f"(f[7])
                : "memory");
        }
    } else {
        // ------------- hash block (hIdx = grp*2 + rem-3): 2 thr/pt -------------
        const int hIdx = grp * 2 + (rem - 3);
        const int pt   = tid >> 1;               // 0..95
        const int half = tid & 1;
        const int p  = hIdx * HPTS + pt;
        const bool valid = (p < npts);
        const int  pl = valid ? p : (npts - 1);
        const int jbase = 2 * half;

        const float2 xv = __ldg((const float2*)x + pl);
        const float x0 = xv.x, x1 = xv.y;

        float w0s[2], w1s[2], f[4];
        int idxs[8];
#pragma unroll
        for (int j = 0; j < 2; j++) {
            const int lj  = jbase + j;                 // 0..3
            const int lvl = NDENSE + lj;
            int li  = (lj < L) ? lj : (L - 1);
            int len = __ldg(lengths + li);             // (res+1)^2, exact in f32
            int res = (int)__fsqrt_rn((float)len) - 1; // exact integer sqrt
            float gs = __fdiv_rn(2048.0f, (float)res); // == f64-then-f32 (proven)

            float q0  = div_full(x0, gs);
            float q1  = div_full(x1, gs);
            float b0f = floorf(q0), b1f = floorf(q1);
            int   b0  = (int)b0f,   b1  = (int)b1f;
            float mn0 = b0f * gs,   mn1 = b1f * gs;
            w0s[j] = __fdividef(x0 - mn0, (mn0 + gs) - mn0);
            w1s[j] = __fdividef(x1 - mn1, (mn1 + gs) - mn1);

            unsigned g0 = (unsigned)b0, g1 = (unsigned)b1;
            unsigned h00 = (g0        ^ (g1        * HPRIME)) & HMASK;
            unsigned h01 = (g0        ^ ((g1 + 1u) * HPRIME)) & HMASK;
            unsigned h10 = ((g0 + 1u) ^ (g1        * HPRIME)) & HMASK;
            unsigned h11 = ((g0 + 1u) ^ ((g1 + 1u) * HPRIME)) & HMASK;

            if ((unsigned)b0 < (unsigned)res && (unsigned)b1 < (unsigned)res) {
                // All 4 corners present in table => searchsorted returns the hash.
                idxs[4 * j + 0] = (int)h00; idxs[4 * j + 1] = (int)h01;
                idxs[4 * j + 2] = (int)h10; idxs[4 * j + 3] = (int)h11;
            } else {
                long long ro = (long long)li * maxP;
                idxs[4 * j + 0] = cons_lookup(tk, tv, ro, len, h00);
                idxs[4 * j + 1] = cons_lookup(tk, tv, ro, len, h01);
                idxs[4 * j + 2] = cons_lookup(tk, tv, ro, len, h10);
                idxs[4 * j + 3] = cons_lookup(tk, tv, ro, len, h11);
            }

            if (valid) {
                float4 v = make_float4((float)idxs[4 * j + 0], (float)idxs[4 * j + 1],
                                       (float)idxs[4 * j + 2], (float)idxs[4 * j + 3]);
                __stcs((float4*)(out + idxbase + ((size_t)lvl * npts + p) * 4), v);
            }
        }

#pragma unroll
        for (int j = 0; j < 2; j++) {
            const int lvl = NDENSE + jbase + j;
            const float2* tb = (const float2*)tables + (size_t)lvl * TSIZE;
            float2 e00 = __ldg(tb + idxs[4 * j + 0]);
            float2 e01 = __ldg(tb + idxs[4 * j + 1]);
            float2 e10 = __ldg(tb + idxs[4 * j + 2]);
            float2 e11 = __ldg(tb + idxs[4 * j + 3]);

            float w0 = w0s[j], w1 = w1s[j];
            float om0 = 1.0f - w0, om1 = 1.0f - w1;
            float c0x = e00.x * om1 + e01.x * w1;
            float c1x = e10.x * om1 + e11.x * w1;
            float c0y = e00.y * om1 + e01.y * w1;
            float c1y = e10.y * om1 + e11.y * w1;
            f[2 * j]     = c0x * om0 + c1x * w0;
            f[2 * j + 1] = c0y * om0 + c1y * w0;
        }

        if (valid) {
            // 16B slice: levels {12,13} at +96B (half=0) or {14,15} at +112B.
            __stcs((float4*)(out + (size_t)p * 32 + 24 + 4 * half),
                   make_float4(f[0], f[1], f[2], f[3]));
        }
    }
}

extern "C" void kernel_launch(void* const* d_in, const int* in_sizes, int n_in,
                              void* d_out, int out_size)
{
    const float* x       = (const float*)d_in[0];
    const float* tables  = (const float*)d_in[1];
    const int*   tk      = (const int*)d_in[2];
    const int*   tv      = (const int*)d_in[3];
    const int*   lengths = (const int*)d_in[4];

    int L    = in_sizes[4];
    int maxP = in_sizes[2] / (L > 0 ? L : 1);
    int npts = in_sizes[0] / 2;

    fill_quad_kernel<<<(QTOTAL + BLK - 1) / BLK, BLK>>>(tables);

    int Nd = (npts + DPTS - 1) / DPTS;
    int Nh = (npts + HPTS - 1) / HPTS;
    int gd = (Nd + 2) / 3, gh = (Nh + 1) / 2;
    int groups = gd > gh ? gd : gh;
    hashgrid_kernel<<<groups * 5, BLKT>>>(x, tables, tk, tv, lengths, L, maxP,
                                          (float*)d_out, npts);
}